// round 13
// baseline (speedup 1.0000x reference)
#include <cuda_runtime.h>
#include <cuda_bf16.h>
#include <cstdint>

#define NN 100000
#define DD 128
#define HH 64
#define KK 8
#define LL 3
#define CC 16
#define EE 1600000

// ---------------- device scratch ----------------
__device__ __align__(128) float g_h[NN * HH];
__device__ __align__(128) float g_agg[NN * HH];
__device__ __align__(128) float g_dn[NN];
__device__ __align__(128) int   g_deg[NN];
__device__ __align__(128) int   g_ptr[NN + 1];
__device__ __align__(128) int   g_cur[NN];
__device__ __align__(128) int   g_bsum[128];
__device__ __align__(128) uint2 g_csr[EE];            // (src, val bits)
__device__ __align__(128) uint2 g_wpack[48 * 2048];
__device__ __align__(128) uint2 g_wpack0[2 * 2048];

extern __shared__ unsigned char dyn_smem[];

__device__ __forceinline__ uint16_t bf16_bits(float v) {
    __nv_bfloat16 b = __float2bfloat16(v);
    return *reinterpret_cast<uint16_t*>(&b);
}
__device__ __forceinline__ float bf16_val(float v) {
    return __bfloat162float(__float2bfloat16(v));
}
__device__ __forceinline__ uint32_t pack2(uint16_t lo, uint16_t hi) {
    return (uint32_t)lo | ((uint32_t)hi << 16);
}

__device__ __forceinline__ void hmma(float* d, const uint32_t* a, uint2 b) {
    asm volatile(
        "mma.sync.aligned.m16n8k16.row.col.f32.bf16.bf16.f32 "
        "{%0,%1,%2,%3}, {%4,%5,%6,%7}, {%8,%9}, {%0,%1,%2,%3};"
        : "+f"(d[0]), "+f"(d[1]), "+f"(d[2]), "+f"(d[3])
        : "r"(a[0]), "r"(a[1]), "r"(a[2]), "r"(a[3]), "r"(b.x), "r"(b.y));
}

__device__ __forceinline__ void cp_async16(void* dst, const void* src) {
    uint32_t d = (uint32_t)__cvta_generic_to_shared(dst);
    asm volatile("cp.async.cg.shared.global [%0], [%1], 16;" :: "r"(d), "l"(src));
}
#define CP_COMMIT() asm volatile("cp.async.commit_group;" ::: "memory")

// ---------------- CSR build kernels ----------------
__global__ void zero_deg_kernel() {
    int i = blockIdx.x * blockDim.x + threadIdx.x;
    if (i < NN) g_deg[i] = 0;
}
__global__ void deg_kernel(const int* __restrict__ col) {
    int e = blockIdx.x * blockDim.x + threadIdx.x;
    if (e < EE) atomicAdd(&g_deg[col[e]], 1);
}
__global__ void __launch_bounds__(1024) scan_block_kernel() {
    __shared__ int s[1024];
    int t = threadIdx.x;
    int i = blockIdx.x * 1024 + t;
    int v = (i < NN) ? g_deg[i] : 0;
    if (i < NN) g_dn[i] = v > 0 ? rsqrtf((float)v) : 0.f;
    s[t] = v;
    __syncthreads();
#pragma unroll
    for (int off = 1; off < 1024; off <<= 1) {
        int x = (t >= off) ? s[t - off] : 0;
        __syncthreads();
        s[t] += x;
        __syncthreads();
    }
    if (i < NN) g_ptr[i] = s[t] - v;  // exclusive within block
    if (t == 1023) g_bsum[blockIdx.x] = s[1023];
}
__global__ void __launch_bounds__(128) scan_bsum_kernel(int nblocks) {
    __shared__ int s[128];
    int t = threadIdx.x;
    int v = (t < nblocks) ? g_bsum[t] : 0;
    s[t] = v;
    __syncthreads();
#pragma unroll
    for (int off = 1; off < 128; off <<= 1) {
        int x = (t >= off) ? s[t - off] : 0;
        __syncthreads();
        s[t] += x;
        __syncthreads();
    }
    if (t < nblocks) g_bsum[t] = s[t] - v;   // exclusive
    if (t == 127) g_ptr[NN] = s[127];
}
__global__ void __launch_bounds__(1024) scan_add_kernel() {
    int i = blockIdx.x * 1024 + threadIdx.x;
    if (i < NN) {
        int p = g_ptr[i] + g_bsum[blockIdx.x];
        g_ptr[i] = p;
        g_cur[i] = p;
    }
}
__global__ void fill_csr_kernel(const int* __restrict__ row, const int* __restrict__ col) {
    int e = blockIdx.x * blockDim.x + threadIdx.x;
    if (e < EE) {
        int c = col[e], r = row[e];
        int p = atomicAdd(&g_cur[c], 1);
        g_csr[p] = make_uint2((unsigned)r, __float_as_uint(g_dn[r] * g_dn[c]));
    }
}

// ---------------- gather: agg[n] = sum_j val_j * h[src_j] (2 nodes/warp, MLP=4) ----------------
__global__ void __launch_bounds__(256) gather_kernel() {
    int n = blockIdx.x * 16 + (threadIdx.x >> 4);
    if (n >= NN) return;
    int lane = threadIdx.x & 15;
    int js = g_ptr[n], je = g_ptr[n + 1];
    const float4* h4 = reinterpret_cast<const float4*>(g_h);
    float4 acc = make_float4(0.f, 0.f, 0.f, 0.f);
    int j = js;
    for (; j + 4 <= je; j += 4) {
        uint2 c0 = g_csr[j], c1 = g_csr[j + 1], c2 = g_csr[j + 2], c3 = g_csr[j + 3];
        float4 a0 = h4[c0.x * 16 + lane];
        float4 a1 = h4[c1.x * 16 + lane];
        float4 a2 = h4[c2.x * 16 + lane];
        float4 a3 = h4[c3.x * 16 + lane];
        float v0 = __uint_as_float(c0.y), v1 = __uint_as_float(c1.y);
        float v2 = __uint_as_float(c2.y), v3 = __uint_as_float(c3.y);
        acc.x += v0 * a0.x; acc.y += v0 * a0.y; acc.z += v0 * a0.z; acc.w += v0 * a0.w;
        acc.x += v1 * a1.x; acc.y += v1 * a1.y; acc.z += v1 * a1.z; acc.w += v1 * a1.w;
        acc.x += v2 * a2.x; acc.y += v2 * a2.y; acc.z += v2 * a2.z; acc.w += v2 * a2.w;
        acc.x += v3 * a3.x; acc.y += v3 * a3.y; acc.z += v3 * a3.z; acc.w += v3 * a3.w;
    }
    for (; j < je; j++) {
        uint2 c = g_csr[j];
        float4 a = h4[c.x * 16 + lane];
        float v = __uint_as_float(c.y);
        acc.x += v * a.x; acc.y += v * a.y; acc.z += v * a.z; acc.w += v * a.w;
    }
    reinterpret_cast<float4*>(g_agg)[n * 16 + lane] = acc;
}

// ---------------- W prepack: bf16 hi/lo split, HMMA B-fragment order ----------------
__device__ __forceinline__ void wpack_img(const float* __restrict__ w, uint2* __restrict__ dst, int sel) {
    for (int i = threadIdx.x; i < 2048; i += 256) {
        int lane = i & 31;
        int nt = (i >> 5) & 7;
        int ks = i >> 8;
        int tig = lane & 3, gid = lane >> 2;
        int n = nt * 8 + gid;
        int k0 = ks * 16 + tig * 2;
        float v0 = w[(k0 + 0) * 64 + n];
        float v1 = w[(k0 + 1) * 64 + n];
        float v2 = w[(k0 + 8) * 64 + n];
        float v3 = w[(k0 + 9) * 64 + n];
        uint16_t h0, h1, h2, h3;
        if (sel == 0) {
            h0 = bf16_bits(v0); h1 = bf16_bits(v1); h2 = bf16_bits(v2); h3 = bf16_bits(v3);
        } else {
            h0 = bf16_bits(v0 - bf16_val(v0));
            h1 = bf16_bits(v1 - bf16_val(v1));
            h2 = bf16_bits(v2 - bf16_val(v2));
            h3 = bf16_bits(v3 - bf16_val(v3));
        }
        dst[i] = make_uint2(pack2(h0, h1), pack2(h2, h3));
    }
}
__global__ void wpack_kernel(const float* __restrict__ cw) {
    int img = blockIdx.x;          // 0..47
    wpack_img(cw + (img >> 1) * 8192, g_wpack + img * 2048, img & 1);
}
__global__ void wpack0_kernel(const float* __restrict__ w0) {
    wpack_img(w0, g_wpack0 + blockIdx.x * 2048, blockIdx.x);
}

// ---------------- smem layout ----------------
#define A_STRIDE 136
#define SM_A_BYTES (128 * A_STRIDE * 2)          // 34816
#define SM_AH 0
#define SM_AL SM_A_BYTES
#define SM_E  (2 * SM_A_BYTES)                   // 69632 (beyond 64KB B ring)
#define SM_EW (SM_E + 128 * 8 * 4)               // 73728
#define SM_H  (SM_EW + 520 * 4)                  // 75808: fp32 h tile 128 x 68
#define CONV_SMEM (SM_H + 128 * 68 * 4)          // 110624
#define FC0_SMEM  (2 * SM_A_BYTES)

// ---------------- fc0 via HMMA: h = relu(x @ w + b) ----------------
__global__ void __launch_bounds__(256, 1) fc0_mma_kernel(const float* __restrict__ x,
                                                         const float* __restrict__ bias) {
    unsigned char* smb = dyn_smem;
    uint16_t* Ah = reinterpret_cast<uint16_t*>(smb + SM_AH);
    uint16_t* Al = reinterpret_cast<uint16_t*>(smb + SM_AL);

    int t = threadIdx.x;
    int wid = t >> 5, lane = t & 31;
    int tig = lane & 3, gid = lane >> 2;
    int n0 = blockIdx.x * 128;

    const float4* x4 = reinterpret_cast<const float4*>(x);
    for (int idx = t; idx < 4096; idx += 256) {
        int r = idx >> 5, j = idx & 31;
        int gn = n0 + r;
        float4 v = make_float4(0.f, 0.f, 0.f, 0.f);
        if (gn < NN) v = x4[gn * 32 + j];
        uint16_t hx = bf16_bits(v.x), hy = bf16_bits(v.y);
        uint16_t hz = bf16_bits(v.z), hw = bf16_bits(v.w);
        uint16_t lx = bf16_bits(v.x - bf16_val(v.x));
        uint16_t ly = bf16_bits(v.y - bf16_val(v.y));
        uint16_t lz = bf16_bits(v.z - bf16_val(v.z));
        uint16_t lw = bf16_bits(v.w - bf16_val(v.w));
        *reinterpret_cast<uint2*>(&Ah[r * A_STRIDE + j * 4]) = make_uint2(pack2(hx, hy), pack2(hz, hw));
        *reinterpret_cast<uint2*>(&Al[r * A_STRIDE + j * 4]) = make_uint2(pack2(lx, ly), pack2(lz, lw));
    }
    __syncthreads();

    uint32_t ah[8][4], al[8][4];
    int fr0 = wid * 16 + gid;
#pragma unroll
    for (int s = 0; s < 8; s++) {
        int kc = s * 16 + tig * 2;
        ah[s][0] = *reinterpret_cast<const uint32_t*>(&Ah[fr0 * A_STRIDE + kc]);
        ah[s][1] = *reinterpret_cast<const uint32_t*>(&Ah[(fr0 + 8) * A_STRIDE + kc]);
        ah[s][2] = *reinterpret_cast<const uint32_t*>(&Ah[fr0 * A_STRIDE + kc + 8]);
        ah[s][3] = *reinterpret_cast<const uint32_t*>(&Ah[(fr0 + 8) * A_STRIDE + kc + 8]);
        al[s][0] = *reinterpret_cast<const uint32_t*>(&Al[fr0 * A_STRIDE + kc]);
        al[s][1] = *reinterpret_cast<const uint32_t*>(&Al[(fr0 + 8) * A_STRIDE + kc]);
        al[s][2] = *reinterpret_cast<const uint32_t*>(&Al[fr0 * A_STRIDE + kc + 8]);
        al[s][3] = *reinterpret_cast<const uint32_t*>(&Al[(fr0 + 8) * A_STRIDE + kc + 8]);
    }

    float acc[8][4];
#pragma unroll
    for (int nt = 0; nt < 8; nt++)
#pragma unroll
        for (int i = 0; i < 4; i++) acc[nt][i] = 0.f;

    const uint2* bh = g_wpack0;
    const uint2* bl = g_wpack0 + 2048;
#pragma unroll
    for (int s = 0; s < 8; s++) {
        uint2 b[8];
#pragma unroll
        for (int nt = 0; nt < 8; nt++) b[nt] = bh[(s * 8 + nt) * 32 + lane];
#pragma unroll
        for (int nt = 0; nt < 8; nt++) hmma(acc[nt], ah[s], b[nt]);
#pragma unroll
        for (int nt = 0; nt < 8; nt++) hmma(acc[nt], al[s], b[nt]);
    }
#pragma unroll
    for (int s = 0; s < 8; s++) {
        uint2 b[8];
#pragma unroll
        for (int nt = 0; nt < 8; nt++) b[nt] = bl[(s * 8 + nt) * 32 + lane];
#pragma unroll
        for (int nt = 0; nt < 8; nt++) hmma(acc[nt], ah[s], b[nt]);
    }

    int gn0 = n0 + wid * 16 + gid;
    int gn1 = gn0 + 8;
#pragma unroll
    for (int nt = 0; nt < 8; nt++) {
        int c = nt * 8 + tig * 2;
        float2 bi = *reinterpret_cast<const float2*>(&bias[c]);
        if (gn0 < NN) {
            float2 o;
            o.x = fmaxf(acc[nt][0] + bi.x, 0.f);
            o.y = fmaxf(acc[nt][1] + bi.y, 0.f);
            *reinterpret_cast<float2*>(&g_h[gn0 * 64 + c]) = o;
        }
        if (gn1 < NN) {
            float2 o;
            o.x = fmaxf(acc[nt][2] + bi.x, 0.f);
            o.y = fmaxf(acc[nt][3] + bi.y, 0.f);
            *reinterpret_cast<float2*>(&g_h[gn1 * 64 + c]) = o;
        }
    }
}

// ---------------- conv layer: K-split warps, smem h tile, gating + mma.sync bf16x3 ----------------
__global__ void __launch_bounds__(256, 1) conv_mma_kernel(const float* __restrict__ ew,
                                                          const float* __restrict__ eb,
                                                          int layer) {
    unsigned char* smb = dyn_smem;
    uint16_t* Ah = reinterpret_cast<uint16_t*>(smb + SM_AH);
    uint16_t* Al = reinterpret_cast<uint16_t*>(smb + SM_AL);
    float* s_e = reinterpret_cast<float*>(smb + SM_E);
    float* s_ew = reinterpret_cast<float*>(smb + SM_EW);
    float* s_h = reinterpret_cast<float*>(smb + SM_H);   // fp32 h tile, stride 68

    int t = threadIdx.x;
    int wid = t >> 5, lane = t & 31;
    int tig = lane & 3, gid = lane >> 2;
    int wk = wid & 1;      // K half
    int wm = wid >> 1;     // M group (32 rows)
    int n0 = blockIdx.x * 128;

    for (int i = t; i < 520; i += 256) s_ew[i] = (i < 512) ? ew[i] : eb[i - 512];

    // ---- build A tile (agg || h, bf16 hi/lo split); stash fp32 h in smem ----
    const float4* agg4 = reinterpret_cast<const float4*>(g_agg);
    const float4* h4 = reinterpret_cast<const float4*>(g_h);
    for (int idx = t; idx < 4096; idx += 256) {
        int r = idx >> 5, j = idx & 31;
        int gn = n0 + r;
        float4 v = make_float4(0.f, 0.f, 0.f, 0.f);
        if (gn < NN) v = (j < 16) ? agg4[gn * 16 + j] : h4[gn * 16 + (j - 16)];
        if (j >= 16) *reinterpret_cast<float4*>(&s_h[r * 68 + (j - 16) * 4]) = v;
        uint16_t hx = bf16_bits(v.x), hy = bf16_bits(v.y);
        uint16_t hz = bf16_bits(v.z), hw = bf16_bits(v.w);
        uint16_t lx = bf16_bits(v.x - bf16_val(v.x));
        uint16_t ly = bf16_bits(v.y - bf16_val(v.y));
        uint16_t lz = bf16_bits(v.z - bf16_val(v.z));
        uint16_t lw = bf16_bits(v.w - bf16_val(v.w));
        *reinterpret_cast<uint2*>(&Ah[r * A_STRIDE + j * 4]) = make_uint2(pack2(hx, hy), pack2(hz, hw));
        *reinterpret_cast<uint2*>(&Al[r * A_STRIDE + j * 4]) = make_uint2(pack2(lx, ly), pack2(lz, lw));
    }
    __syncthreads();

    // ---- A fragments: 2 m-frags x 4 k-steps (own K half) ----
    uint32_t ah[2][4][4], al[2][4][4];
    int fr0 = wm * 32 + gid;
#pragma unroll
    for (int m = 0; m < 2; m++) {
        int base = fr0 + m * 16;
#pragma unroll
        for (int s = 0; s < 4; s++) {
            int kc = (wk * 4 + s) * 16 + tig * 2;
            ah[m][s][0] = *reinterpret_cast<const uint32_t*>(&Ah[base * A_STRIDE + kc]);
            ah[m][s][1] = *reinterpret_cast<const uint32_t*>(&Ah[(base + 8) * A_STRIDE + kc]);
            ah[m][s][2] = *reinterpret_cast<const uint32_t*>(&Ah[base * A_STRIDE + kc + 8]);
            ah[m][s][3] = *reinterpret_cast<const uint32_t*>(&Ah[(base + 8) * A_STRIDE + kc + 8]);
            al[m][s][0] = *reinterpret_cast<const uint32_t*>(&Al[base * A_STRIDE + kc]);
            al[m][s][1] = *reinterpret_cast<const uint32_t*>(&Al[(base + 8) * A_STRIDE + kc]);
            al[m][s][2] = *reinterpret_cast<const uint32_t*>(&Al[base * A_STRIDE + kc + 8]);
            al[m][s][3] = *reinterpret_cast<const uint32_t*>(&Al[(base + 8) * A_STRIDE + kc + 8]);
        }
    }
    __syncthreads();   // done reading A smem; B ring may overwrite it

    const uint2* wp = g_wpack + layer * 8 * 4096;   // 4096 uint2 (32KB) per head

    // prefetch heads 0,1 into slots 0,1
    {
        uint2* dst0 = reinterpret_cast<uint2*>(smb);
        const uint2* s0 = wp;
        for (int i = 0; i < 8; i++) cp_async16(dst0 + (i * 256 + t) * 2, s0 + (i * 256 + t) * 2);
        CP_COMMIT();
        uint2* dst1 = reinterpret_cast<uint2*>(smb + 32768);
        const uint2* s1 = wp + 4096;
        for (int i = 0; i < 8; i++) cp_async16(dst1 + (i * 256 + t) * 2, s1 + (i * 256 + t) * 2);
        CP_COMMIT();
    }

    // ---- gating (threads 0..127, one node each) from smem h tile ----
    if (t < 128) {
        float lg[8];
#pragma unroll
        for (int k = 0; k < 8; k++) lg[k] = s_ew[512 + k];
#pragma unroll 8
        for (int f = 0; f < 64; f += 4) {
            float4 hv4 = *reinterpret_cast<const float4*>(&s_h[t * 68 + f]);
            float hv[4] = {hv4.x, hv4.y, hv4.z, hv4.w};
#pragma unroll
            for (int q = 0; q < 4; q++) {
                float4 w0 = *reinterpret_cast<const float4*>(&s_ew[(f + q) * 8]);
                float4 w1 = *reinterpret_cast<const float4*>(&s_ew[(f + q) * 8 + 4]);
                lg[0] += hv[q] * w0.x; lg[1] += hv[q] * w0.y; lg[2] += hv[q] * w0.z; lg[3] += hv[q] * w0.w;
                lg[4] += hv[q] * w1.x; lg[5] += hv[q] * w1.y; lg[6] += hv[q] * w1.z; lg[7] += hv[q] * w1.w;
            }
        }
        float m = -1e30f;
#pragma unroll
        for (int k = 0; k < 8; k++) m = fmaxf(m, lg[k]);
        float sum = 0.f;
#pragma unroll
        for (int k = 0; k < 8; k++) { lg[k] = expf(lg[k] - m); sum += lg[k]; }
        float inv = 1.f / sum;
#pragma unroll
        for (int k = 0; k < 8; k++) {
            float pi = lg[k] * inv;
            s_e[t * 8 + k] = (pi > 0.1f) ? pi : 0.f;
        }
    }

    // ---- main MMA loop over 8 heads (nt-outer, partial K per warp) ----
    float acc[2][8][4];
#pragma unroll
    for (int m = 0; m < 2; m++)
#pragma unroll
        for (int nt = 0; nt < 8; nt++)
#pragma unroll
            for (int i = 0; i < 4; i++) acc[m][nt][i] = 0.f;

#pragma unroll 1
    for (int k = 0; k < 8; k++) {
        if (k < 7) asm volatile("cp.async.wait_group 1;" ::: "memory");
        else       asm volatile("cp.async.wait_group 0;" ::: "memory");
        __syncthreads();   // B slot k&1 visible CTA-wide; also publishes s_e on k=0

        int slot = k & 1;
        const uint2* bh = reinterpret_cast<const uint2*>(smb + slot * 32768);
        const uint2* bl = bh + 2048;

        float e00 = s_e[(fr0) * 8 + k];
        float e01 = s_e[(fr0 + 8) * 8 + k];
        float e10 = s_e[(fr0 + 16) * 8 + k];
        float e11 = s_e[(fr0 + 24) * 8 + k];

#pragma unroll
        for (int nt = 0; nt < 8; nt++) {
            float acck[2][4] = {};
#pragma unroll
            for (int s = 0; s < 4; s++) {
                uint2 b = bh[((wk * 4 + s) * 8 + nt) * 32 + lane];
                hmma(acck[0], ah[0][s], b);
                hmma(acck[0], al[0][s], b);
                hmma(acck[1], ah[1][s], b);
                hmma(acck[1], al[1][s], b);
            }
#pragma unroll
            for (int s = 0; s < 4; s++) {
                uint2 b = bl[((wk * 4 + s) * 8 + nt) * 32 + lane];
                hmma(acck[0], ah[0][s], b);
                hmma(acck[1], ah[1][s], b);
            }
            acc[0][nt][0] += e00 * acck[0][0];
            acc[0][nt][1] += e00 * acck[0][1];
            acc[0][nt][2] += e01 * acck[0][2];
            acc[0][nt][3] += e01 * acck[0][3];
            acc[1][nt][0] += e10 * acck[1][0];
            acc[1][nt][1] += e10 * acck[1][1];
            acc[1][nt][2] += e11 * acck[1][2];
            acc[1][nt][3] += e11 * acck[1][3];
        }

        if (k + 2 < 8) {
            __syncthreads();   // all warps done with slot before overwrite
            uint2* dst = reinterpret_cast<uint2*>(smb + slot * 32768);
            const uint2* src = wp + (k + 2) * 4096;
            for (int i = 0; i < 8; i++) cp_async16(dst + (i * 256 + t) * 2, src + (i * 256 + t) * 2);
            CP_COMMIT();
        }
    }

    // ---- cross-warp K reduction (wk=1 -> smem staging -> wk=0 adds) ----
    float* stg = reinterpret_cast<float*>(smb);
    if (wk == 1) {
#pragma unroll
        for (int m = 0; m < 2; m++)
#pragma unroll
            for (int nt = 0; nt < 8; nt++)
#pragma unroll
                for (int i = 0; i < 4; i++)
                    stg[(m * 32 + nt * 4 + i) * 128 + wm * 32 + lane] = acc[m][nt][i];
    }
    __syncthreads();

    if (wk == 0) {
#pragma unroll
        for (int m = 0; m < 2; m++)
#pragma unroll
            for (int nt = 0; nt < 8; nt++)
#pragma unroll
                for (int i = 0; i < 4; i++)
                    acc[m][nt][i] += stg[(m * 32 + nt * 4 + i) * 128 + wm * 32 + lane];

        // ---- epilogue: h = relu(acc + h_smem), write g_h ----
#pragma unroll
        for (int m = 0; m < 2; m++) {
            int r0 = fr0 + m * 16;
            int gn0 = n0 + r0;
            int gn1 = gn0 + 8;
#pragma unroll
            for (int nt = 0; nt < 8; nt++) {
                int c = nt * 8 + tig * 2;
                if (gn0 < NN) {
                    float2 hv = *reinterpret_cast<const float2*>(&s_h[r0 * 68 + c]);
                    float2 o;
                    o.x = fmaxf(acc[m][nt][0] + hv.x, 0.f);
                    o.y = fmaxf(acc[m][nt][1] + hv.y, 0.f);
                    *reinterpret_cast<float2*>(&g_h[gn0 * 64 + c]) = o;
                }
                if (gn1 < NN) {
                    float2 hv = *reinterpret_cast<const float2*>(&s_h[(r0 + 8) * 68 + c]);
                    float2 o;
                    o.x = fmaxf(acc[m][nt][2] + hv.x, 0.f);
                    o.y = fmaxf(acc[m][nt][3] + hv.y, 0.f);
                    *reinterpret_cast<float2*>(&g_h[gn1 * 64 + c]) = o;
                }
            }
        }
    }
}

// ---------------- fc1 ----------------
__global__ void __launch_bounds__(256) fc1_kernel(const float* __restrict__ w,
                                                  const float* __restrict__ b,
                                                  float* __restrict__ out) {
    __shared__ float s_w[64 * 16];
    __shared__ float s_b[16];
    int t = threadIdx.x;
    for (int idx = t; idx < 64 * 16; idx += 256) s_w[idx] = w[idx];
    if (t < 16) s_b[t] = b[t];
    __syncthreads();
    int n = blockIdx.x * 256 + t;
    if (n < NN) {
        float hr[64];
#pragma unroll
        for (int i = 0; i < 16; i++) {
            float4 v = *reinterpret_cast<const float4*>(&g_h[n * 64 + i * 4]);
            hr[4 * i] = v.x; hr[4 * i + 1] = v.y; hr[4 * i + 2] = v.z; hr[4 * i + 3] = v.w;
        }
        float o[16];
#pragma unroll
        for (int c = 0; c < 16; c++) {
            float s = s_b[c];
#pragma unroll
            for (int f = 0; f < 64; f++) s += hr[f] * s_w[f * 16 + c];
            o[c] = s;
        }
#pragma unroll
        for (int i = 0; i < 4; i++) {
            *reinterpret_cast<float4*>(&out[n * 16 + i * 4]) =
                make_float4(o[4 * i], o[4 * i + 1], o[4 * i + 2], o[4 * i + 3]);
        }
    }
}

// ---------------- launch ----------------
extern "C" void kernel_launch(void* const* d_in, const int* in_sizes, int n_in,
                              void* d_out, int out_size) {
    const float* x     = (const float*)d_in[0];
    const int*   ei    = (const int*)  d_in[1];
    const float* fc0w  = (const float*)d_in[2];
    const float* fc0b  = (const float*)d_in[3];
    const float* fc1w  = (const float*)d_in[4];
    const float* fc1b  = (const float*)d_in[5];
    const float* envw  = (const float*)d_in[6];
    const float* envb  = (const float*)d_in[7];
    const float* convw = (const float*)d_in[8];
    float* out = (float*)d_out;

    const int* row = ei;
    const int* col = ei + EE;

    cudaFuncSetAttribute(fc0_mma_kernel, cudaFuncAttributeMaxDynamicSharedMemorySize, FC0_SMEM);
    cudaFuncSetAttribute(conv_mma_kernel, cudaFuncAttributeMaxDynamicSharedMemorySize, CONV_SMEM);

    const int nscan = (NN + 1023) / 1024;   // 98

    static cudaStream_t s2 = nullptr;
    static cudaEvent_t evF = nullptr, evJ = nullptr;
    if (s2 == nullptr) {
        cudaStreamCreateWithFlags(&s2, cudaStreamNonBlocking);
        cudaEventCreateWithFlags(&evF, cudaEventDisableTiming);
        cudaEventCreateWithFlags(&evJ, cudaEventDisableTiming);
    }

    // fork: CSR build on s2, wpack/fc0 on main — fully independent branches
    cudaEventRecord(evF, 0);
    cudaStreamWaitEvent(s2, evF, 0);

    zero_deg_kernel<<<(NN + 255) / 256, 256, 0, s2>>>();
    deg_kernel<<<(EE + 255) / 256, 256, 0, s2>>>(col);
    scan_block_kernel<<<nscan, 1024, 0, s2>>>();     // also computes g_dn
    scan_bsum_kernel<<<1, 128, 0, s2>>>(nscan);
    scan_add_kernel<<<nscan, 1024, 0, s2>>>();
    fill_csr_kernel<<<(EE + 255) / 256, 256, 0, s2>>>(row, col);
    cudaEventRecord(evJ, s2);

    wpack0_kernel<<<2, 256>>>(fc0w);
    fc0_mma_kernel<<<(NN + 127) / 128, 256, FC0_SMEM>>>(x, fc0b);
    wpack_kernel<<<48, 256>>>(convw);

    // join
    cudaStreamWaitEvent(0, evJ, 0);

    for (int i = 0; i < LL; i++) {
        gather_kernel<<<(NN + 15) / 16, 256>>>();
        conv_mma_kernel<<<(NN + 127) / 128, 256, CONV_SMEM>>>(
            envw + i * 2 * HH * KK, envb + i * KK, i);
    }

    fc1_kernel<<<(NN + 255) / 256, 256>>>(fc1w, fc1b, out);
}

// round 14
// speedup vs baseline: 1.0895x; 1.0895x over previous
#include <cuda_runtime.h>
#include <cuda_bf16.h>
#include <cstdint>

#define NN 100000
#define DD 128
#define HH 64
#define KK 8
#define LL 3
#define CC 16
#define EE 1600000

// ---------------- device scratch ----------------
__device__ __align__(128) float g_h[NN * HH];
__device__ __align__(128) uint32_t g_apk[NN * 64];   // packed agg: [n][0:32]=hi, [32:64]=lo
__device__ __align__(128) uint32_t g_hpk[NN * 64];   // packed h:   [n][0:32]=hi, [32:64]=lo
__device__ __align__(128) float g_dn[NN];
__device__ __align__(128) int   g_deg[NN];
__device__ __align__(128) int   g_ptr[NN + 1];
__device__ __align__(128) int   g_cur[NN];
__device__ __align__(128) int   g_bsum[128];
__device__ __align__(128) uint2 g_csr[EE];            // (src, val bits)
__device__ __align__(128) uint2 g_wpack[48 * 2048];
__device__ __align__(128) uint2 g_wpack0[2 * 2048];

extern __shared__ unsigned char dyn_smem[];

__device__ __forceinline__ uint16_t bf16_bits(float v) {
    __nv_bfloat16 b = __float2bfloat16(v);
    return *reinterpret_cast<uint16_t*>(&b);
}
__device__ __forceinline__ float bf16_val(float v) {
    return __bfloat162float(__float2bfloat16(v));
}
__device__ __forceinline__ uint32_t pack2(uint16_t lo, uint16_t hi) {
    return (uint32_t)lo | ((uint32_t)hi << 16);
}

__device__ __forceinline__ void hmma(float* d, const uint32_t* a, uint2 b) {
    asm volatile(
        "mma.sync.aligned.m16n8k16.row.col.f32.bf16.bf16.f32 "
        "{%0,%1,%2,%3}, {%4,%5,%6,%7}, {%8,%9}, {%0,%1,%2,%3};"
        : "+f"(d[0]), "+f"(d[1]), "+f"(d[2]), "+f"(d[3])
        : "r"(a[0]), "r"(a[1]), "r"(a[2]), "r"(a[3]), "r"(b.x), "r"(b.y));
}

__device__ __forceinline__ void cp_async16(void* dst, const void* src) {
    uint32_t d = (uint32_t)__cvta_generic_to_shared(dst);
    asm volatile("cp.async.cg.shared.global [%0], [%1], 16;" :: "r"(d), "l"(src));
}
#define CP_COMMIT() asm volatile("cp.async.commit_group;" ::: "memory")

// ---------------- CSR build kernels ----------------
__global__ void zero_deg_kernel() {
    int i = blockIdx.x * blockDim.x + threadIdx.x;
    if (i < NN) g_deg[i] = 0;
}
__global__ void deg_kernel(const int* __restrict__ col) {
    int e = blockIdx.x * blockDim.x + threadIdx.x;
    if (e < EE) atomicAdd(&g_deg[col[e]], 1);
}
__global__ void __launch_bounds__(1024) scan_block_kernel() {
    __shared__ int s[1024];
    int t = threadIdx.x;
    int i = blockIdx.x * 1024 + t;
    int v = (i < NN) ? g_deg[i] : 0;
    if (i < NN) g_dn[i] = v > 0 ? rsqrtf((float)v) : 0.f;
    s[t] = v;
    __syncthreads();
#pragma unroll
    for (int off = 1; off < 1024; off <<= 1) {
        int x = (t >= off) ? s[t - off] : 0;
        __syncthreads();
        s[t] += x;
        __syncthreads();
    }
    if (i < NN) g_ptr[i] = s[t] - v;
    if (t == 1023) g_bsum[blockIdx.x] = s[1023];
}
__global__ void __launch_bounds__(128) scan_bsum_kernel(int nblocks) {
    __shared__ int s[128];
    int t = threadIdx.x;
    int v = (t < nblocks) ? g_bsum[t] : 0;
    s[t] = v;
    __syncthreads();
#pragma unroll
    for (int off = 1; off < 128; off <<= 1) {
        int x = (t >= off) ? s[t - off] : 0;
        __syncthreads();
        s[t] += x;
        __syncthreads();
    }
    if (t < nblocks) g_bsum[t] = s[t] - v;
    if (t == 127) g_ptr[NN] = s[127];
}
__global__ void __launch_bounds__(1024) scan_add_kernel() {
    int i = blockIdx.x * 1024 + threadIdx.x;
    if (i < NN) {
        int p = g_ptr[i] + g_bsum[blockIdx.x];
        g_ptr[i] = p;
        g_cur[i] = p;
    }
}
__global__ void fill_csr_kernel(const int* __restrict__ row, const int* __restrict__ col) {
    int e = blockIdx.x * blockDim.x + threadIdx.x;
    if (e < EE) {
        int c = col[e], r = row[e];
        int p = atomicAdd(&g_cur[c], 1);
        g_csr[p] = make_uint2((unsigned)r, __float_as_uint(g_dn[r] * g_dn[c]));
    }
}

// ---------------- gather: packed bf16 agg (2 nodes/warp, MLP=4) ----------------
__global__ void __launch_bounds__(256) gather_kernel() {
    int n = blockIdx.x * 16 + (threadIdx.x >> 4);
    if (n >= NN) return;
    int lane = threadIdx.x & 15;
    int js = g_ptr[n], je = g_ptr[n + 1];
    const float4* h4 = reinterpret_cast<const float4*>(g_h);
    float4 acc = make_float4(0.f, 0.f, 0.f, 0.f);
    int j = js;
    for (; j + 4 <= je; j += 4) {
        uint2 c0 = g_csr[j], c1 = g_csr[j + 1], c2 = g_csr[j + 2], c3 = g_csr[j + 3];
        float4 a0 = h4[c0.x * 16 + lane];
        float4 a1 = h4[c1.x * 16 + lane];
        float4 a2 = h4[c2.x * 16 + lane];
        float4 a3 = h4[c3.x * 16 + lane];
        float v0 = __uint_as_float(c0.y), v1 = __uint_as_float(c1.y);
        float v2 = __uint_as_float(c2.y), v3 = __uint_as_float(c3.y);
        acc.x += v0 * a0.x; acc.y += v0 * a0.y; acc.z += v0 * a0.z; acc.w += v0 * a0.w;
        acc.x += v1 * a1.x; acc.y += v1 * a1.y; acc.z += v1 * a1.z; acc.w += v1 * a1.w;
        acc.x += v2 * a2.x; acc.y += v2 * a2.y; acc.z += v2 * a2.z; acc.w += v2 * a2.w;
        acc.x += v3 * a3.x; acc.y += v3 * a3.y; acc.z += v3 * a3.z; acc.w += v3 * a3.w;
    }
    for (; j < je; j++) {
        uint2 c = g_csr[j];
        float4 a = h4[c.x * 16 + lane];
        float v = __uint_as_float(c.y);
        acc.x += v * a.x; acc.y += v * a.y; acc.z += v * a.z; acc.w += v * a.w;
    }
    // bf16 hi/lo split, packed
    uint32_t h0 = pack2(bf16_bits(acc.x), bf16_bits(acc.y));
    uint32_t h1 = pack2(bf16_bits(acc.z), bf16_bits(acc.w));
    uint32_t l0 = pack2(bf16_bits(acc.x - bf16_val(acc.x)), bf16_bits(acc.y - bf16_val(acc.y)));
    uint32_t l1 = pack2(bf16_bits(acc.z - bf16_val(acc.z)), bf16_bits(acc.w - bf16_val(acc.w)));
    *reinterpret_cast<uint2*>(&g_apk[n * 64 + 2 * lane]) = make_uint2(h0, h1);
    *reinterpret_cast<uint2*>(&g_apk[n * 64 + 32 + 2 * lane]) = make_uint2(l0, l1);
}

// ---------------- W prepack: bf16 hi/lo split, HMMA B-fragment order ----------------
__device__ __forceinline__ void wpack_img(const float* __restrict__ w, uint2* __restrict__ dst, int sel) {
    for (int i = threadIdx.x; i < 2048; i += 256) {
        int lane = i & 31;
        int nt = (i >> 5) & 7;
        int ks = i >> 8;
        int tig = lane & 3, gid = lane >> 2;
        int n = nt * 8 + gid;
        int k0 = ks * 16 + tig * 2;
        float v0 = w[(k0 + 0) * 64 + n];
        float v1 = w[(k0 + 1) * 64 + n];
        float v2 = w[(k0 + 8) * 64 + n];
        float v3 = w[(k0 + 9) * 64 + n];
        uint16_t h0, h1, h2, h3;
        if (sel == 0) {
            h0 = bf16_bits(v0); h1 = bf16_bits(v1); h2 = bf16_bits(v2); h3 = bf16_bits(v3);
        } else {
            h0 = bf16_bits(v0 - bf16_val(v0));
            h1 = bf16_bits(v1 - bf16_val(v1));
            h2 = bf16_bits(v2 - bf16_val(v2));
            h3 = bf16_bits(v3 - bf16_val(v3));
        }
        dst[i] = make_uint2(pack2(h0, h1), pack2(h2, h3));
    }
}
__global__ void wpack_kernel(const float* __restrict__ cw) {
    int img = blockIdx.x;
    wpack_img(cw + (img >> 1) * 8192, g_wpack + img * 2048, img & 1);
}
__global__ void wpack0_kernel(const float* __restrict__ w0) {
    wpack_img(w0, g_wpack0 + blockIdx.x * 2048, blockIdx.x);
}

// ---------------- smem layout ----------------
#define A_STRIDE 136
#define SM_A_BYTES (128 * A_STRIDE * 2)          // 34816
#define SM_AH 0
#define SM_AL SM_A_BYTES
#define SM_E  (2 * SM_A_BYTES)                   // 69632
#define SM_EW (SM_E + 128 * 8 * 4)               // 73728
#define CONV_SMEM (SM_EW + 520 * 4)              // 75808
#define FC0_SMEM  (2 * SM_A_BYTES)

// ---------------- fc0 via HMMA: h = relu(x @ w + b); also writes packed h ----------------
__global__ void __launch_bounds__(256, 1) fc0_mma_kernel(const float* __restrict__ x,
                                                         const float* __restrict__ bias) {
    unsigned char* smb = dyn_smem;
    uint16_t* Ah = reinterpret_cast<uint16_t*>(smb + SM_AH);
    uint16_t* Al = reinterpret_cast<uint16_t*>(smb + SM_AL);

    int t = threadIdx.x;
    int wid = t >> 5, lane = t & 31;
    int tig = lane & 3, gid = lane >> 2;
    int n0 = blockIdx.x * 128;

    const float4* x4 = reinterpret_cast<const float4*>(x);
    for (int idx = t; idx < 4096; idx += 256) {
        int r = idx >> 5, j = idx & 31;
        int gn = n0 + r;
        float4 v = make_float4(0.f, 0.f, 0.f, 0.f);
        if (gn < NN) v = x4[gn * 32 + j];
        uint16_t hx = bf16_bits(v.x), hy = bf16_bits(v.y);
        uint16_t hz = bf16_bits(v.z), hw = bf16_bits(v.w);
        uint16_t lx = bf16_bits(v.x - bf16_val(v.x));
        uint16_t ly = bf16_bits(v.y - bf16_val(v.y));
        uint16_t lz = bf16_bits(v.z - bf16_val(v.z));
        uint16_t lw = bf16_bits(v.w - bf16_val(v.w));
        *reinterpret_cast<uint2*>(&Ah[r * A_STRIDE + j * 4]) = make_uint2(pack2(hx, hy), pack2(hz, hw));
        *reinterpret_cast<uint2*>(&Al[r * A_STRIDE + j * 4]) = make_uint2(pack2(lx, ly), pack2(lz, lw));
    }
    __syncthreads();

    uint32_t ah[8][4], al[8][4];
    int fr0 = wid * 16 + gid;
#pragma unroll
    for (int s = 0; s < 8; s++) {
        int kc = s * 16 + tig * 2;
        ah[s][0] = *reinterpret_cast<const uint32_t*>(&Ah[fr0 * A_STRIDE + kc]);
        ah[s][1] = *reinterpret_cast<const uint32_t*>(&Ah[(fr0 + 8) * A_STRIDE + kc]);
        ah[s][2] = *reinterpret_cast<const uint32_t*>(&Ah[fr0 * A_STRIDE + kc + 8]);
        ah[s][3] = *reinterpret_cast<const uint32_t*>(&Ah[(fr0 + 8) * A_STRIDE + kc + 8]);
        al[s][0] = *reinterpret_cast<const uint32_t*>(&Al[fr0 * A_STRIDE + kc]);
        al[s][1] = *reinterpret_cast<const uint32_t*>(&Al[(fr0 + 8) * A_STRIDE + kc]);
        al[s][2] = *reinterpret_cast<const uint32_t*>(&Al[fr0 * A_STRIDE + kc + 8]);
        al[s][3] = *reinterpret_cast<const uint32_t*>(&Al[(fr0 + 8) * A_STRIDE + kc + 8]);
    }

    float acc[8][4];
#pragma unroll
    for (int nt = 0; nt < 8; nt++)
#pragma unroll
        for (int i = 0; i < 4; i++) acc[nt][i] = 0.f;

    const uint2* bh = g_wpack0;
    const uint2* bl = g_wpack0 + 2048;
#pragma unroll
    for (int s = 0; s < 8; s++) {
        uint2 b[8];
#pragma unroll
        for (int nt = 0; nt < 8; nt++) b[nt] = bh[(s * 8 + nt) * 32 + lane];
#pragma unroll
        for (int nt = 0; nt < 8; nt++) hmma(acc[nt], ah[s], b[nt]);
#pragma unroll
        for (int nt = 0; nt < 8; nt++) hmma(acc[nt], al[s], b[nt]);
    }
#pragma unroll
    for (int s = 0; s < 8; s++) {
        uint2 b[8];
#pragma unroll
        for (int nt = 0; nt < 8; nt++) b[nt] = bl[(s * 8 + nt) * 32 + lane];
#pragma unroll
        for (int nt = 0; nt < 8; nt++) hmma(acc[nt], ah[s], b[nt]);
    }

    int gn0 = n0 + wid * 16 + gid;
    int gn1 = gn0 + 8;
#pragma unroll
    for (int nt = 0; nt < 8; nt++) {
        int c = nt * 8 + tig * 2;
        float2 bi = *reinterpret_cast<const float2*>(&bias[c]);
        if (gn0 < NN) {
            float2 o;
            o.x = fmaxf(acc[nt][0] + bi.x, 0.f);
            o.y = fmaxf(acc[nt][1] + bi.y, 0.f);
            *reinterpret_cast<float2*>(&g_h[gn0 * 64 + c]) = o;
            g_hpk[gn0 * 64 + (c >> 1)] = pack2(bf16_bits(o.x), bf16_bits(o.y));
            g_hpk[gn0 * 64 + 32 + (c >> 1)] =
                pack2(bf16_bits(o.x - bf16_val(o.x)), bf16_bits(o.y - bf16_val(o.y)));
        }
        if (gn1 < NN) {
            float2 o;
            o.x = fmaxf(acc[nt][2] + bi.x, 0.f);
            o.y = fmaxf(acc[nt][3] + bi.y, 0.f);
            *reinterpret_cast<float2*>(&g_h[gn1 * 64 + c]) = o;
            g_hpk[gn1 * 64 + (c >> 1)] = pack2(bf16_bits(o.x), bf16_bits(o.y));
            g_hpk[gn1 * 64 + 32 + (c >> 1)] =
                pack2(bf16_bits(o.x - bf16_val(o.x)), bf16_bits(o.y - bf16_val(o.y)));
        }
    }
}

// ---------------- conv layer: cp.async A tile from packed, K-split warps, bf16x3 ----------------
__global__ void __launch_bounds__(256, 1) conv_mma_kernel(const float* __restrict__ ew,
                                                          const float* __restrict__ eb,
                                                          int layer) {
    unsigned char* smb = dyn_smem;
    uint16_t* Ah = reinterpret_cast<uint16_t*>(smb + SM_AH);
    uint16_t* Al = reinterpret_cast<uint16_t*>(smb + SM_AL);
    uint32_t* Ah32 = reinterpret_cast<uint32_t*>(Ah);
    uint32_t* Al32 = reinterpret_cast<uint32_t*>(Al);
    float* s_e = reinterpret_cast<float*>(smb + SM_E);
    float* s_ew = reinterpret_cast<float*>(smb + SM_EW);

    int t = threadIdx.x;
    int wid = t >> 5, lane = t & 31;
    int tig = lane & 3, gid = lane >> 2;
    int wk = wid & 1;      // K half
    int wm = wid >> 1;     // M group (32 rows)
    int n0 = blockIdx.x * 128;

    for (int i = t; i < 520; i += 256) s_ew[i] = (i < 512) ? ew[i] : eb[i - 512];

    // ---- A tile via cp.async from packed agg/h (no converts) ----
    // seg layout per row: part0 Ah-agg, part1 Ah-h, part2 Al-agg, part3 Al-h; 128B each.
    for (int idx = t; idx < 4096; idx += 256) {
        int q = idx & 7;            // 16B unit within 128B segment
        int seg = idx >> 3;
        int r = seg >> 2, part = seg & 3;
        int gn = n0 + r;
        uint32_t* dstbase = (part < 2) ? Ah32 : Al32;
        uint32_t* dst = dstbase + r * 68 + (part & 1) * 32 + q * 4;
        if (gn < NN) {
            const uint32_t* srcb = (part & 1) ? g_hpk : g_apk;
            const uint32_t* src = srcb + gn * 64 + ((part < 2) ? 0 : 32) + q * 4;
            cp_async16(dst, src);
        } else {
            *reinterpret_cast<uint4*>(dst) = make_uint4(0u, 0u, 0u, 0u);
        }
    }
    CP_COMMIT();
    __syncthreads();   // s_ew visible for gating

    // ---- gating (threads 0..127) from global h — overlaps the A cp.async ----
    const float4* h4 = reinterpret_cast<const float4*>(g_h);
    if (t < 128) {
        int gn = n0 + t;
        float lg[8];
#pragma unroll
        for (int k = 0; k < 8; k++) lg[k] = s_ew[512 + k];
        if (gn < NN) {
#pragma unroll
            for (int i = 0; i < 16; i++) {
                float4 v = h4[gn * 16 + i];
                float hv[4] = {v.x, v.y, v.z, v.w};
#pragma unroll
                for (int qq = 0; qq < 4; qq++) {
                    int f = i * 4 + qq;
                    float4 w0 = *reinterpret_cast<const float4*>(&s_ew[f * 8]);
                    float4 w1 = *reinterpret_cast<const float4*>(&s_ew[f * 8 + 4]);
                    lg[0] += hv[qq] * w0.x; lg[1] += hv[qq] * w0.y;
                    lg[2] += hv[qq] * w0.z; lg[3] += hv[qq] * w0.w;
                    lg[4] += hv[qq] * w1.x; lg[5] += hv[qq] * w1.y;
                    lg[6] += hv[qq] * w1.z; lg[7] += hv[qq] * w1.w;
                }
            }
        }
        float m = -1e30f;
#pragma unroll
        for (int k = 0; k < 8; k++) m = fmaxf(m, lg[k]);
        float sum = 0.f;
#pragma unroll
        for (int k = 0; k < 8; k++) { lg[k] = expf(lg[k] - m); sum += lg[k]; }
        float inv = 1.f / sum;
#pragma unroll
        for (int k = 0; k < 8; k++) {
            float pi = lg[k] * inv;
            s_e[t * 8 + k] = (pi > 0.1f) ? pi : 0.f;
        }
    }

    // ---- wait A copies, extract fragments ----
    asm volatile("cp.async.wait_group 0;" ::: "memory");
    __syncthreads();

    uint32_t ah[2][4][4], al[2][4][4];
    int fr0 = wm * 32 + gid;
#pragma unroll
    for (int m = 0; m < 2; m++) {
        int base = fr0 + m * 16;
#pragma unroll
        for (int s = 0; s < 4; s++) {
            int kc = (wk * 4 + s) * 16 + tig * 2;
            ah[m][s][0] = *reinterpret_cast<const uint32_t*>(&Ah[base * A_STRIDE + kc]);
            ah[m][s][1] = *reinterpret_cast<const uint32_t*>(&Ah[(base + 8) * A_STRIDE + kc]);
            ah[m][s][2] = *reinterpret_cast<const uint32_t*>(&Ah[base * A_STRIDE + kc + 8]);
            ah[m][s][3] = *reinterpret_cast<const uint32_t*>(&Ah[(base + 8) * A_STRIDE + kc + 8]);
            al[m][s][0] = *reinterpret_cast<const uint32_t*>(&Al[base * A_STRIDE + kc]);
            al[m][s][1] = *reinterpret_cast<const uint32_t*>(&Al[(base + 8) * A_STRIDE + kc]);
            al[m][s][2] = *reinterpret_cast<const uint32_t*>(&Al[base * A_STRIDE + kc + 8]);
            al[m][s][3] = *reinterpret_cast<const uint32_t*>(&Al[(base + 8) * A_STRIDE + kc + 8]);
        }
    }
    __syncthreads();   // done reading A smem; B ring may overwrite

    const uint2* wp = g_wpack + layer * 8 * 4096;

    // prefetch heads 0,1 into slots 0,1
    {
        uint2* dst0 = reinterpret_cast<uint2*>(smb);
        const uint2* s0 = wp;
        for (int i = 0; i < 8; i++) cp_async16(dst0 + (i * 256 + t) * 2, s0 + (i * 256 + t) * 2);
        CP_COMMIT();
        uint2* dst1 = reinterpret_cast<uint2*>(smb + 32768);
        const uint2* s1 = wp + 4096;
        for (int i = 0; i < 8; i++) cp_async16(dst1 + (i * 256 + t) * 2, s1 + (i * 256 + t) * 2);
        CP_COMMIT();
    }

    // ---- main MMA loop over 8 heads ----
    float acc[2][8][4];
#pragma unroll
    for (int m = 0; m < 2; m++)
#pragma unroll
        for (int nt = 0; nt < 8; nt++)
#pragma unroll
            for (int i = 0; i < 4; i++) acc[m][nt][i] = 0.f;

#pragma unroll 1
    for (int k = 0; k < 8; k++) {
        if (k < 7) asm volatile("cp.async.wait_group 1;" ::: "memory");
        else       asm volatile("cp.async.wait_group 0;" ::: "memory");
        __syncthreads();

        int slot = k & 1;
        const uint2* bh = reinterpret_cast<const uint2*>(smb + slot * 32768);
        const uint2* bl = bh + 2048;

        float e00 = s_e[(fr0) * 8 + k];
        float e01 = s_e[(fr0 + 8) * 8 + k];
        float e10 = s_e[(fr0 + 16) * 8 + k];
        float e11 = s_e[(fr0 + 24) * 8 + k];

#pragma unroll
        for (int nt = 0; nt < 8; nt++) {
            float acck[2][4] = {};
#pragma unroll
            for (int s = 0; s < 4; s++) {
                uint2 b = bh[((wk * 4 + s) * 8 + nt) * 32 + lane];
                hmma(acck[0], ah[0][s], b);
                hmma(acck[0], al[0][s], b);
                hmma(acck[1], ah[1][s], b);
                hmma(acck[1], al[1][s], b);
            }
#pragma unroll
            for (int s = 0; s < 4; s++) {
                uint2 b = bl[((wk * 4 + s) * 8 + nt) * 32 + lane];
                hmma(acck[0], ah[0][s], b);
                hmma(acck[1], ah[1][s], b);
            }
            acc[0][nt][0] += e00 * acck[0][0];
            acc[0][nt][1] += e00 * acck[0][1];
            acc[0][nt][2] += e01 * acck[0][2];
            acc[0][nt][3] += e01 * acck[0][3];
            acc[1][nt][0] += e10 * acck[1][0];
            acc[1][nt][1] += e10 * acck[1][1];
            acc[1][nt][2] += e11 * acck[1][2];
            acc[1][nt][3] += e11 * acck[1][3];
        }

        if (k + 2 < 8) {
            __syncthreads();
            uint2* dst = reinterpret_cast<uint2*>(smb + slot * 32768);
            const uint2* src = wp + (k + 2) * 4096;
            for (int i = 0; i < 8; i++) cp_async16(dst + (i * 256 + t) * 2, src + (i * 256 + t) * 2);
            CP_COMMIT();
        }
    }

    // ---- cross-warp K reduction ----
    float* stg = reinterpret_cast<float*>(smb);
    if (wk == 1) {
#pragma unroll
        for (int m = 0; m < 2; m++)
#pragma unroll
            for (int nt = 0; nt < 8; nt++)
#pragma unroll
                for (int i = 0; i < 4; i++)
                    stg[(m * 32 + nt * 4 + i) * 128 + wm * 32 + lane] = acc[m][nt][i];
    }
    __syncthreads();

    if (wk == 0) {
#pragma unroll
        for (int m = 0; m < 2; m++)
#pragma unroll
            for (int nt = 0; nt < 8; nt++)
#pragma unroll
                for (int i = 0; i < 4; i++)
                    acc[m][nt][i] += stg[(m * 32 + nt * 4 + i) * 128 + wm * 32 + lane];

        // ---- epilogue: h = relu(acc + h), write fp32 h + packed h ----
#pragma unroll
        for (int m = 0; m < 2; m++) {
            int gn0 = n0 + fr0 + m * 16;
            int gn1 = gn0 + 8;
#pragma unroll
            for (int nt = 0; nt < 8; nt++) {
                int c = nt * 8 + tig * 2;
                if (gn0 < NN) {
                    float2 hv = *reinterpret_cast<const float2*>(&g_h[gn0 * 64 + c]);
                    float2 o;
                    o.x = fmaxf(acc[m][nt][0] + hv.x, 0.f);
                    o.y = fmaxf(acc[m][nt][1] + hv.y, 0.f);
                    *reinterpret_cast<float2*>(&g_h[gn0 * 64 + c]) = o;
                    g_hpk[gn0 * 64 + (c >> 1)] = pack2(bf16_bits(o.x), bf16_bits(o.y));
                    g_hpk[gn0 * 64 + 32 + (c >> 1)] =
                        pack2(bf16_bits(o.x - bf16_val(o.x)), bf16_bits(o.y - bf16_val(o.y)));
                }
                if (gn1 < NN) {
                    float2 hv = *reinterpret_cast<const float2*>(&g_h[gn1 * 64 + c]);
                    float2 o;
                    o.x = fmaxf(acc[m][nt][2] + hv.x, 0.f);
                    o.y = fmaxf(acc[m][nt][3] + hv.y, 0.f);
                    *reinterpret_cast<float2*>(&g_h[gn1 * 64 + c]) = o;
                    g_hpk[gn1 * 64 + (c >> 1)] = pack2(bf16_bits(o.x), bf16_bits(o.y));
                    g_hpk[gn1 * 64 + 32 + (c >> 1)] =
                        pack2(bf16_bits(o.x - bf16_val(o.x)), bf16_bits(o.y - bf16_val(o.y)));
                }
            }
        }
    }
}

// ---------------- fc1 ----------------
__global__ void __launch_bounds__(256) fc1_kernel(const float* __restrict__ w,
                                                  const float* __restrict__ b,
                                                  float* __restrict__ out) {
    __shared__ float s_w[64 * 16];
    __shared__ float s_b[16];
    int t = threadIdx.x;
    for (int idx = t; idx < 64 * 16; idx += 256) s_w[idx] = w[idx];
    if (t < 16) s_b[t] = b[t];
    __syncthreads();
    int n = blockIdx.x * 256 + t;
    if (n < NN) {
        float hr[64];
#pragma unroll
        for (int i = 0; i < 16; i++) {
            float4 v = *reinterpret_cast<const float4*>(&g_h[n * 64 + i * 4]);
            hr[4 * i] = v.x; hr[4 * i + 1] = v.y; hr[4 * i + 2] = v.z; hr[4 * i + 3] = v.w;
        }
        float o[16];
#pragma unroll
        for (int c = 0; c < 16; c++) {
            float s = s_b[c];
#pragma unroll
            for (int f = 0; f < 64; f++) s += hr[f] * s_w[f * 16 + c];
            o[c] = s;
        }
#pragma unroll
        for (int i = 0; i < 4; i++) {
            *reinterpret_cast<float4*>(&out[n * 16 + i * 4]) =
                make_float4(o[4 * i], o[4 * i + 1], o[4 * i + 2], o[4 * i + 3]);
        }
    }
}

// ---------------- launch ----------------
extern "C" void kernel_launch(void* const* d_in, const int* in_sizes, int n_in,
                              void* d_out, int out_size) {
    const float* x     = (const float*)d_in[0];
    const int*   ei    = (const int*)  d_in[1];
    const float* fc0w  = (const float*)d_in[2];
    const float* fc0b  = (const float*)d_in[3];
    const float* fc1w  = (const float*)d_in[4];
    const float* fc1b  = (const float*)d_in[5];
    const float* envw  = (const float*)d_in[6];
    const float* envb  = (const float*)d_in[7];
    const float* convw = (const float*)d_in[8];
    float* out = (float*)d_out;

    const int* row = ei;
    const int* col = ei + EE;

    cudaFuncSetAttribute(fc0_mma_kernel, cudaFuncAttributeMaxDynamicSharedMemorySize, FC0_SMEM);
    cudaFuncSetAttribute(conv_mma_kernel, cudaFuncAttributeMaxDynamicSharedMemorySize, CONV_SMEM);

    const int nscan = (NN + 1023) / 1024;

    static cudaStream_t s2 = nullptr;
    static cudaEvent_t evF = nullptr, evJ = nullptr;
    if (s2 == nullptr) {
        cudaStreamCreateWithFlags(&s2, cudaStreamNonBlocking);
        cudaEventCreateWithFlags(&evF, cudaEventDisableTiming);
        cudaEventCreateWithFlags(&evJ, cudaEventDisableTiming);
    }

    cudaEventRecord(evF, 0);
    cudaStreamWaitEvent(s2, evF, 0);

    zero_deg_kernel<<<(NN + 255) / 256, 256, 0, s2>>>();
    deg_kernel<<<(EE + 255) / 256, 256, 0, s2>>>(col);
    scan_block_kernel<<<nscan, 1024, 0, s2>>>();
    scan_bsum_kernel<<<1, 128, 0, s2>>>(nscan);
    scan_add_kernel<<<nscan, 1024, 0, s2>>>();
    fill_csr_kernel<<<(EE + 255) / 256, 256, 0, s2>>>(row, col);
    cudaEventRecord(evJ, s2);

    wpack0_kernel<<<2, 256>>>(fc0w);
    fc0_mma_kernel<<<(NN + 127) / 128, 256, FC0_SMEM>>>(x, fc0b);
    wpack_kernel<<<48, 256>>>(convw);

    cudaStreamWaitEvent(0, evJ, 0);

    for (int i = 0; i < LL; i++) {
        gather_kernel<<<(NN + 15) / 16, 256>>>();
        conv_mma_kernel<<<(NN + 127) / 128, 256, CONV_SMEM>>>(
            envw + i * 2 * HH * KK, envb + i * KK, i);
    }

    fc1_kernel<<<(NN + 255) / 256, 256>>>(fc1w, fc1b, out);
}